// round 1
// baseline (speedup 1.0000x reference)
#include <cuda_runtime.h>
#include <cuda_bf16.h>
#include <cstdint>

// ----------------------------------------------------------------------------
// BlockSparseLinear: out[M, N] = x[M, K] @ (W .* mask)^T + bias
//   M = B*S = 8192, K = IN = 4096, N = OUT = 4096
//   mask is block-structured: 16x16 blocks, uniform within a block, ~10% nonzero.
//
// Strategy (round 1, SIMT fp32 baseline):
//   1. detect mask element width (bool(1B) vs int32/float32(4B)) from byte patterns
//   2. build per-output-block compacted list of nonzero 16-wide K-blocks
//   3. block-sparse SGEMM: CTA = 512 rows x 16 cols, loops only nonzero K-blocks
// ----------------------------------------------------------------------------

#define NBLK      256          // 4096 / 16 blocks along each of N and K
#define BLK       16
#define KDIM      4096
#define NDIM      4096
#define MTILE     512
#define XS_STRIDE 516          // padded row stride (floats) for xs[k][m]

__device__ int g_mask_elt4;            // 1 if mask elements are 4 bytes wide
__device__ int g_bcount[NBLK];         // nonzero K-blocks per output block
__device__ int g_blist[NBLK * NBLK];   // compacted K-block indices per output block

// --------------------------------------------------------------------------
// Detect mask element width.
//  - float32: 1.0f contains bytes 0x80 / 0x3F  -> some byte > 1
//  - bool/uint8: 16-wide blocks of ones -> runs of consecutive 1-bytes
//  - int32: isolated 1-bytes (01 00 00 00), never adjacent, all bytes <= 1
// elt4 = any_gt1 || !any_adjacent_pair
// --------------------------------------------------------------------------
__global__ void detect_mask_kernel(const unsigned char* __restrict__ mask) {
    __shared__ int s_gt1, s_pair;
    if (threadIdx.x == 0) { s_gt1 = 0; s_pair = 0; }
    __syncthreads();
    const int SCAN = 1 << 20;  // 1 MB: far beyond enough blocks for both hypotheses
    for (int i = threadIdx.x; i < SCAN; i += blockDim.x) {
        unsigned char a = mask[i];
        if (a > 1) s_gt1 = 1;
        if (a == 1 && mask[i + 1] == 1) s_pair = 1;
    }
    __syncthreads();
    if (threadIdx.x == 0) g_mask_elt4 = (s_gt1 || !s_pair) ? 1 : 0;
}

// --------------------------------------------------------------------------
// Build per-output-block compacted nonzero K-block lists.
// Mask is uniform within each 16x16 block, so one probe per block suffices.
// --------------------------------------------------------------------------
__global__ void build_block_list(const void* __restrict__ mask) {
    const int ob = blockIdx.x;       // output block row (16 output cols)
    const int ib = threadIdx.x;      // candidate K-block
    __shared__ unsigned char flags[NBLK];

    size_t idx = (size_t)(ob * BLK) * KDIM + (size_t)ib * BLK;
    bool nz;
    if (g_mask_elt4)
        nz = ((const unsigned int*)mask)[idx] != 0u;   // int32 or float32 bit pattern
    else
        nz = ((const unsigned char*)mask)[idx] != 0;
    flags[ib] = nz ? 1 : 0;
    __syncthreads();

    if (threadIdx.x == 0) {
        int c = 0;
        for (int i = 0; i < NBLK; ++i)
            if (flags[i]) g_blist[ob * NBLK + c++] = i;
        g_bcount[ob] = c;
    }
}

// --------------------------------------------------------------------------
// Block-sparse SGEMM.
//   grid = (256 output blocks, M/512 row tiles), 128 threads.
//   Thread register tile: 8 rows (two 4-row halves, 256 apart) x 8 cols
//   (two 4-col halves, 8 apart). x tile staged transposed in smem as
//   xs[k][m] (stride 516 -> conflict-free vectorized reads).
// --------------------------------------------------------------------------
__global__ void __launch_bounds__(128, 4)
sparse_gemm(const float* __restrict__ x,
            const float* __restrict__ w,
            const float* __restrict__ bias,
            float* __restrict__ out) {
    const int ob = blockIdx.x;
    const int m0 = blockIdx.y * MTILE;

    __shared__ __align__(16) float xs[BLK * XS_STRIDE];  // [k][m], 33 KB
    __shared__ __align__(16) float ws[BLK * BLK];        // [k][oc], 1 KB

    const int tid = threadIdx.x;
    const int tx  = tid & 1;    // column half selector
    const int tr  = tid >> 1;   // 0..63 row group

    float acc[2][2][4][4];
#pragma unroll
    for (int rh = 0; rh < 2; ++rh)
#pragma unroll
        for (int ch = 0; ch < 2; ++ch)
#pragma unroll
            for (int r = 0; r < 4; ++r)
#pragma unroll
                for (int c = 0; c < 4; ++c)
                    acc[rh][ch][r][c] = 0.0f;

    const float4* xg = reinterpret_cast<const float4*>(x);
    const float4* wg = reinterpret_cast<const float4*>(w);

    const int cnt = g_bcount[ob];
    for (int bi = 0; bi < cnt; ++bi) {
        const int ib = g_blist[ob * NBLK + bi];

        // ---- stage x tile [MTILE x 16] transposed into xs[k][m] ----
#pragma unroll
        for (int j = 0; j < 16; ++j) {
            int id = tid + j * 128;           // 0..2047 float4 units
            int m  = id >> 2;                 // 0..511
            int kq = id & 3;                  // which float4 along k
            float4 v = xg[(size_t)(m0 + m) * (KDIM / 4) + ib * 4 + kq];
            xs[(kq * 4 + 0) * XS_STRIDE + m] = v.x;
            xs[(kq * 4 + 1) * XS_STRIDE + m] = v.y;
            xs[(kq * 4 + 2) * XS_STRIDE + m] = v.z;
            xs[(kq * 4 + 3) * XS_STRIDE + m] = v.w;
        }
        // ---- stage weight block [16 x 16] transposed into ws[k][oc] ----
        if (tid < 64) {
            int oc = tid >> 2;
            int kq = tid & 3;
            float4 v = wg[(size_t)(ob * BLK + oc) * (KDIM / 4) + ib * 4 + kq];
            ws[(kq * 4 + 0) * BLK + oc] = v.x;
            ws[(kq * 4 + 1) * BLK + oc] = v.y;
            ws[(kq * 4 + 2) * BLK + oc] = v.z;
            ws[(kq * 4 + 3) * BLK + oc] = v.w;
        }
        __syncthreads();

        // ---- compute 16 k-steps, 64 FMA per thread per step ----
#pragma unroll
        for (int k = 0; k < BLK; ++k) {
            float4 a0 = *reinterpret_cast<const float4*>(&xs[k * XS_STRIDE + tr * 4]);
            float4 a1 = *reinterpret_cast<const float4*>(&xs[k * XS_STRIDE + 256 + tr * 4]);
            float4 b0 = *reinterpret_cast<const float4*>(&ws[k * BLK + tx * 4]);
            float4 b1 = *reinterpret_cast<const float4*>(&ws[k * BLK + 8 + tx * 4]);
            float av[2][4] = {{a0.x, a0.y, a0.z, a0.w}, {a1.x, a1.y, a1.z, a1.w}};
            float bv[2][4] = {{b0.x, b0.y, b0.z, b0.w}, {b1.x, b1.y, b1.z, b1.w}};
#pragma unroll
            for (int rh = 0; rh < 2; ++rh)
#pragma unroll
                for (int r = 0; r < 4; ++r)
#pragma unroll
                    for (int ch = 0; ch < 2; ++ch)
#pragma unroll
                        for (int c = 0; c < 4; ++c)
                            acc[rh][ch][r][c] = fmaf(av[rh][r], bv[ch][c],
                                                     acc[rh][ch][r][c]);
        }
        __syncthreads();
    }

    // ---- epilogue: add bias, store ----
    const float4* bias4 = reinterpret_cast<const float4*>(bias);
    float4 bb0 = bias4[ob * 4 + tx];
    float4 bb1 = bias4[ob * 4 + 2 + tx];
    float4* out4 = reinterpret_cast<float4*>(out);

#pragma unroll
    for (int rh = 0; rh < 2; ++rh) {
#pragma unroll
        for (int r = 0; r < 4; ++r) {
            int row = m0 + rh * 256 + tr * 4 + r;
            float4 o0, o1;
            o0.x = acc[rh][0][r][0] + bb0.x;
            o0.y = acc[rh][0][r][1] + bb0.y;
            o0.z = acc[rh][0][r][2] + bb0.z;
            o0.w = acc[rh][0][r][3] + bb0.w;
            o1.x = acc[rh][1][r][0] + bb1.x;
            o1.y = acc[rh][1][r][1] + bb1.y;
            o1.z = acc[rh][1][r][2] + bb1.z;
            o1.w = acc[rh][1][r][3] + bb1.w;
            size_t base = (size_t)row * (NDIM / 4) + ob * 4;
            out4[base + tx]     = o0;
            out4[base + 2 + tx] = o1;
        }
    }
}

extern "C" void kernel_launch(void* const* d_in, const int* in_sizes, int n_in,
                              void* d_out, int out_size) {
    const float* x    = (const float*)d_in[0];   // [B, S, IN] fp32
    const float* w    = (const float*)d_in[1];   // [OUT, IN] fp32
    const float* bias = (const float*)d_in[2];   // [OUT] fp32
    const void*  mask = d_in[3];                 // [OUT, IN] bool/int/float
    float* out = (float*)d_out;                  // [B, S, OUT] fp32

    const int M = in_sizes[0] / KDIM;            // 8192

    detect_mask_kernel<<<1, 256>>>((const unsigned char*)mask);
    build_block_list<<<NBLK, NBLK>>>(mask);

    dim3 grid(NBLK, M / MTILE);
    sparse_gemm<<<grid, 128>>>(x, w, bias, out);
}